// round 14
// baseline (speedup 1.0000x reference)
#include <cuda_runtime.h>
#include <cuda_bf16.h>
#include <cstdint>
#include <cstddef>

#define TT 1024
#define II 64
#define HH 128
#define NCTA 128

typedef unsigned long long u64;

// ---- loop-kernel smem layout (bytes) ----
// weights: [7 slots][4 kq][256 colidx] x 16B (each 16B = 8 k as packed bf16 pairs)
// slot stride = 4*256*16 = 16384 ; region = 7*16384 = 114688
#define OFF_WS  0
#define OFF_GS  114688   // float [4 kq][4 r][512 col] partial gate sums (32 KB)
#define OFF_H   147456   // float [4][128] hidden state
#define OFF_WEF 149504   // float [128]
#define OFF_BE  150016   // float [4]
#define SMEM_BYTES 150032

// ---- xproj smem layout (floats) ----
#define XROW 260
#define WROW 516
#define XP_SMEM_FLOATS (64 * XROW + 64 * WROW)
#define XP_SMEM_BYTES  (XP_SMEM_FLOATS * 4)   // 198656

// xp scratch: [b][t][g] fp32, bias pre-added (+pad so s+1 prefetch at last step is safe)
__device__ float g_xp[(size_t)512 * TT * 512 + 1024];

__device__ __forceinline__ u64 fma2(u64 a, u64 b, u64 c) {
    u64 d;
    asm("fma.rn.f32x2 %0, %1, %2, %3;" : "=l"(d) : "l"(a), "l"(b), "l"(c));
    return d;
}
__device__ __forceinline__ u64 add2(u64 a, u64 b) {
    u64 d;
    asm("add.rn.f32x2 %0, %1, %2;" : "=l"(d) : "l"(a), "l"(b));
    return d;
}
__device__ __forceinline__ void lds_v2(uint32_t a, u64& v0, u64& v1) {
    asm volatile("ld.shared.v2.u64 {%0,%1}, [%2];" : "=l"(v0), "=l"(v1) : "r"(a));
}
__device__ __forceinline__ void lds_v4_u32(uint32_t a, uint32_t& x, uint32_t& y,
                                           uint32_t& z, uint32_t& w) {
    asm volatile("ld.shared.v4.u32 {%0,%1,%2,%3}, [%4];"
                 : "=r"(x), "=r"(y), "=r"(z), "=r"(w) : "r"(a));
}
__device__ __forceinline__ float2 unpack2(u64 v) {
    float2 r;
    asm("mov.b64 {%0,%1}, %2;" : "=f"(r.x), "=f"(r.y) : "l"(v));
    return r;
}
__device__ __forceinline__ u64 pack2(float lo, float hi) {
    u64 v;
    asm("mov.b64 %0, {%1,%2};" : "=l"(v) : "f"(lo), "f"(hi));
    return v;
}
__device__ __forceinline__ u64 splat2(float v) {
    u64 r;
    asm("mov.b64 %0, {%1,%1};" : "=l"(r) : "f"(v));
    return r;
}
// widen packed bf16 pair (u32) to f32x2 (u64): pure bit ops, 2 ALU + pack
__device__ __forceinline__ u64 bf2(uint32_t p) {
    uint32_t lo = p << 16;
    uint32_t hi = p & 0xffff0000u;
    u64 v;
    asm("mov.b64 %0, {%1,%2};" : "=l"(v) : "r"(lo), "r"(hi));
    return v;
}
__device__ __forceinline__ uint32_t pack_bf16(float a, float b) {
    __nv_bfloat162 h = __floats2bfloat162_rn(a, b);   // a -> low half
    uint32_t r;
    asm("mov.b32 %0, %1;" : "=r"(r) : "r"(*reinterpret_cast<uint32_t*>(&h)));
    return r;
}
__device__ __forceinline__ float sigmoid_f(float x) {
    return __fdividef(1.0f, 1.0f + __expf(-x));
}
__device__ __forceinline__ float tanh_f(float x) {
    return __fdividef(2.0f, 1.0f + __expf(-2.0f * x)) - 1.0f;
}

// ================= prologue: xp[b][s][g] = x[b][s][:] . W_ih[g][:] + b_ih[g] + b_hh[g] ======
// Register-tiled SGEMM (structure identical to R13 + bias fold).
__global__ void __launch_bounds__(512, 1)
xproj_kernel(const float* __restrict__ x, const float* __restrict__ W_ih,
             const float* __restrict__ b_ih, const float* __restrict__ b_hh)
{
    extern __shared__ float sm[];
    const int t    = threadIdx.x;
    const int b    = blockIdx.x >> 3;
    const int sblk = ((blockIdx.x >> 1) & 3) * 256;
    const int gh   = (blockIdx.x & 1) * 256;

    float* xT = sm;               // [64][XROW]
    float* wT = sm + 64 * XROW;   // [64][WROW]

    {
        const int sl = t >> 6, k = t & 63;
        #pragma unroll
        for (int r = 0; r < 32; ++r)
            xT[k * XROW + r * 8 + sl] =
                x[((size_t)b * TT + sblk + r * 8 + sl) * II + k];
    }
    {
        const int gl0 = t >> 6, k = t & 63;
        #pragma unroll
        for (int r = 0; r < 32; ++r) {
            int gl = r * 8 + gl0;
            int u = gl >> 3, half = (gl >> 2) & 1, j = gl & 3;
            wT[k * WROW + half * 256 + u * 4 + j] = W_ih[(gh + gl) * II + k];
        }
    }
    __syncthreads();

    const int gg  = t & 31;
    const int sgp = t >> 5;
    const uint32_t sbase = (uint32_t)__cvta_generic_to_shared(sm);
    const uint32_t axb = sbase + (sgp * 8) * 4;
    const uint32_t awb = sbase + 64 * XROW * 4 + gg * 16;

    // per-thread bias pairs for its 8 g columns
    u64 bp[4];
    {
        const float* bi = b_ih + gh + gg * 8;
        const float* bh = b_hh + gh + gg * 8;
        #pragma unroll
        for (int j = 0; j < 4; ++j)
            bp[j] = pack2(bi[2 * j] + bh[2 * j], bi[2 * j + 1] + bh[2 * j + 1]);
    }

    #pragma unroll 1
    for (int p = 0; p < 2; ++p) {
        u64 acc[32];
        #pragma unroll
        for (int q = 0; q < 32; ++q) acc[q] = 0ull;

        uint32_t ax = axb + p * 512;
        uint32_t aw = awb;

        #pragma unroll 4
        for (int k = 0; k < 64; ++k) {
            u64 xa, xb, xc, xd, w0, w1, w2, w3;
            lds_v2(ax, xa, xb);
            lds_v2(ax + 16, xc, xd);
            lds_v2(aw, w0, w1);
            lds_v2(aw + 1024, w2, w3);
            ax += XROW * 4; aw += WROW * 4;

            float2 x01 = unpack2(xa), x23 = unpack2(xb);
            float2 x45 = unpack2(xc), x67 = unpack2(xd);
            u64 s0 = splat2(x01.x), s1 = splat2(x01.y);
            u64 s2 = splat2(x23.x), s3 = splat2(x23.y);
            u64 s4 = splat2(x45.x), s5 = splat2(x45.y);
            u64 s6 = splat2(x67.x), s7 = splat2(x67.y);

            acc[0]  = fma2(w0, s0, acc[0]);   acc[1]  = fma2(w1, s0, acc[1]);
            acc[2]  = fma2(w2, s0, acc[2]);   acc[3]  = fma2(w3, s0, acc[3]);
            acc[4]  = fma2(w0, s1, acc[4]);   acc[5]  = fma2(w1, s1, acc[5]);
            acc[6]  = fma2(w2, s1, acc[6]);   acc[7]  = fma2(w3, s1, acc[7]);
            acc[8]  = fma2(w0, s2, acc[8]);   acc[9]  = fma2(w1, s2, acc[9]);
            acc[10] = fma2(w2, s2, acc[10]);  acc[11] = fma2(w3, s2, acc[11]);
            acc[12] = fma2(w0, s3, acc[12]);  acc[13] = fma2(w1, s3, acc[13]);
            acc[14] = fma2(w2, s3, acc[14]);  acc[15] = fma2(w3, s3, acc[15]);
            acc[16] = fma2(w0, s4, acc[16]);  acc[17] = fma2(w1, s4, acc[17]);
            acc[18] = fma2(w2, s4, acc[18]);  acc[19] = fma2(w3, s4, acc[19]);
            acc[20] = fma2(w0, s5, acc[20]);  acc[21] = fma2(w1, s5, acc[21]);
            acc[22] = fma2(w2, s5, acc[22]);  acc[23] = fma2(w3, s5, acc[23]);
            acc[24] = fma2(w0, s6, acc[24]);  acc[25] = fma2(w1, s6, acc[25]);
            acc[26] = fma2(w2, s6, acc[26]);  acc[27] = fma2(w3, s6, acc[27]);
            acc[28] = fma2(w0, s7, acc[28]);  acc[29] = fma2(w1, s7, acc[29]);
            acc[30] = fma2(w2, s7, acc[30]);  acc[31] = fma2(w3, s7, acc[31]);
        }

        #pragma unroll
        for (int i = 0; i < 8; ++i) {
            size_t srow = (size_t)b * TT + sblk + p * 128 + sgp * 8 + i;
            float* dp = &g_xp[srow * 512 + gh + gg * 8];
            u64 o0 = add2(acc[i * 4 + 0], bp[0]);
            u64 o1 = add2(acc[i * 4 + 1], bp[1]);
            u64 o2 = add2(acc[i * 4 + 2], bp[2]);
            u64 o3 = add2(acc[i * 4 + 3], bp[3]);
            reinterpret_cast<ulonglong2*>(dp)[0] = make_ulonglong2(o0, o1);
            reinterpret_cast<ulonglong2*>(dp)[1] = make_ulonglong2(o2, o3);
        }
    }
}

// ================= sequential LSTM loop: 128 CTAs x 1024 threads =================
// thread: colidx = t&255 -> gate columns (colidx, colidx+256); kq = t>>8 -> k in [32kq, 32kq+32)
// weights: c0 k 0..7 fp32 in regs; c0 k 8..31 + c1 k 0..31 as bf16 in smem (7 slots).
__global__ void __launch_bounds__(1024, 1)
lstm_loop_kernel(const float* __restrict__ W_hh,
                 const float* __restrict__ W1, const float* __restrict__ b1,
                 const float* __restrict__ W2, const float* __restrict__ b2,
                 float* __restrict__ out)
{
    extern __shared__ char smem[];
    const int t      = threadIdx.x;
    const int colidx = t & 255;
    const int kq     = t >> 8;
    const int kb     = kq * 32;
    const int c0     = colidx;
    const int c1     = colidx + 256;
    const int r0     = blockIdx.x * 4;
    const uint32_t sb = (uint32_t)__cvta_generic_to_shared(smem);

    // register weights: W_hh[c0][kb .. kb+7] as 4 u64 fp32 pairs
    u64 wA[4];
    {
        const u64* p = reinterpret_cast<const u64*>(W_hh + c0 * HH + kb);
        #pragma unroll
        for (int q = 0; q < 4; ++q) wA[q] = p[q];
    }

    // bf16 smem slots: 0..2 = c0 k kb+8..kb+31 ; 3..6 = c1 k kb..kb+31
    {
        const float* w0p = W_hh + c0 * HH + kb;
        const float* w1p = W_hh + c1 * HH + kb;
        #pragma unroll
        for (int s2 = 0; s2 < 3; ++s2) {
            uint4 v;
            v.x = pack_bf16(w0p[8 + s2 * 8 + 0], w0p[8 + s2 * 8 + 1]);
            v.y = pack_bf16(w0p[8 + s2 * 8 + 2], w0p[8 + s2 * 8 + 3]);
            v.z = pack_bf16(w0p[8 + s2 * 8 + 4], w0p[8 + s2 * 8 + 5]);
            v.w = pack_bf16(w0p[8 + s2 * 8 + 6], w0p[8 + s2 * 8 + 7]);
            *reinterpret_cast<uint4*>(smem + OFF_WS + ((s2 * 4 + kq) * 256 + colidx) * 16) = v;
        }
        #pragma unroll
        for (int s2 = 0; s2 < 4; ++s2) {
            uint4 v;
            v.x = pack_bf16(w1p[s2 * 8 + 0], w1p[s2 * 8 + 1]);
            v.y = pack_bf16(w1p[s2 * 8 + 2], w1p[s2 * 8 + 3]);
            v.z = pack_bf16(w1p[s2 * 8 + 4], w1p[s2 * 8 + 5]);
            v.w = pack_bf16(w1p[s2 * 8 + 6], w1p[s2 * 8 + 7]);
            *reinterpret_cast<uint4*>(smem + OFF_WS + (((s2 + 3) * 4 + kq) * 256 + colidx) * 16) = v;
        }
    }

    float* gs   = reinterpret_cast<float*>(smem + OFF_GS);
    float* hs   = reinterpret_cast<float*>(smem + OFF_H);
    float* weff = reinterpret_cast<float*>(smem + OFF_WEF);
    float* beff = reinterpret_cast<float*>(smem + OFF_BE);

    if (t < 512) hs[t] = 0.0f;
    if (t >= 512 && t < 640) {
        float s = 0.0f;
        for (int m = 0; m < 256; ++m) s += W2[m] * W1[m * HH + (t - 512)];
        weff[t - 512] = s;
    }
    if (t == 640) {
        float s = b2[0];
        for (int m = 0; m < 256; ++m) s += W2[m] * b1[m];
        beff[0] = s;
    }

    // ---- phase-B per-thread state (threads 0..511): row br, h-column bj ----
    const int br = (t >> 7) & 3;
    const int bj = t & 127;
    const float* xpp = g_xp + ((size_t)(r0 + br) * TT) * 512 + bj;
    float xv0 = 0.f, xv1 = 0.f, xv2 = 0.f, xv3 = 0.f;
    float cval = 0.0f;
    if (t < 512) {
        xv0 = __ldg(xpp);
        xv1 = __ldg(xpp + 128);
        xv2 = __ldg(xpp + 256);
        xv3 = __ldg(xpp + 384);
    }

    const uint32_t aW = sb + OFF_WS + (kq * 256 + colidx) * 16;   // slot stride 16384
    const uint32_t aH = sb + OFF_H + kb * 4;

    __syncthreads();

    #pragma unroll 1
    for (int s = 0; s < TT; ++s) {
        // ---------------- phase A: partial gate sums over this thread's 32 k ----------------
        u64 acc0[4], acc1[4];
        #pragma unroll
        for (int r = 0; r < 4; ++r) { acc0[r] = 0ull; acc1[r] = 0ull; }

        #pragma unroll
        for (int gp = 0; gp < 4; ++gp) {       // 8 k per gp
            uint32_t q0, q1, q2, q3;
            lds_v4_u32(aW + (3 + gp) * 16384, q0, q1, q2, q3);
            u64 wb0 = bf2(q0), wb1 = bf2(q1), wb2 = bf2(q2), wb3 = bf2(q3);
            u64 wa0, wa1, wa2, wa3;
            if (gp == 0) { wa0 = wA[0]; wa1 = wA[1]; wa2 = wA[2]; wa3 = wA[3]; }
            else {
                uint32_t r0q, r1q, r2q, r3q;
                lds_v4_u32(aW + (gp - 1) * 16384, r0q, r1q, r2q, r3q);
                wa0 = bf2(r0q); wa1 = bf2(r1q); wa2 = bf2(r2q); wa3 = bf2(r3q);
            }
            #pragma unroll
            for (int r = 0; r < 4; ++r) {
                u64 p0, p1, p2, p3;
                lds_v2(aH + r * 512 + gp * 32, p0, p1);
                lds_v2(aH + r * 512 + gp * 32 + 16, p2, p3);
                acc0[r] = fma2(wa0, p0, acc0[r]);  acc0[r] = fma2(wa1, p1, acc0[r]);
                acc0[r] = fma2(wa2, p2, acc0[r]);  acc0[r] = fma2(wa3, p3, acc0[r]);
                acc1[r] = fma2(wb0, p0, acc1[r]);  acc1[r] = fma2(wb1, p1, acc1[r]);
                acc1[r] = fma2(wb2, p2, acc1[r]);  acc1[r] = fma2(wb3, p3, acc1[r]);
            }
        }

        #pragma unroll
        for (int r = 0; r < 4; ++r) {
            float2 f0 = unpack2(acc0[r]);
            float2 f1 = unpack2(acc1[r]);
            gs[(kq * 4 + r) * 512 + c0] = f0.x + f0.y;
            gs[(kq * 4 + r) * 512 + c1] = f1.x + f1.y;
        }
        __syncthreads();

        // ---------------- phase B: reduce partials, activations, state update ----------------
        if (t < 512) {
            const float* xn = xpp + (size_t)(s + 1) * 512;
            float xn0 = __ldg(xn), xn1 = __ldg(xn + 128), xn2 = __ldg(xn + 256), xn3 = __ldg(xn + 384);

            float pi = xv0, pf = xv1, pg = xv2, po = xv3;   // biases already folded into xp
            #pragma unroll
            for (int q = 0; q < 4; ++q) {
                const int base = (q * 4 + br) * 512 + bj;
                pi += gs[base];
                pf += gs[base + 128];
                pg += gs[base + 256];
                po += gs[base + 384];
            }
            float ig = sigmoid_f(pi);
            float fg = sigmoid_f(pf);
            float gv = tanh_f(pg);
            float og = sigmoid_f(po);
            cval = fg * cval + ig * gv;
            hs[br * HH + bj] = og * tanh_f(cval);
            xv0 = xn0; xv1 = xn1; xv2 = xn2; xv3 = xn3;
        }
        __syncthreads();
    }

    // ---------------- fused fc1+fc2 epilogue ----------------
    if (t < 4) {
        float s = beff[0];
        #pragma unroll 8
        for (int j = 0; j < HH; ++j) s += hs[t * HH + j] * weff[j];
        out[r0 + t] = s;
    }
}

extern "C" void kernel_launch(void* const* d_in, const int* in_sizes, int n_in,
                              void* d_out, int out_size) {
    const float* x    = (const float*)d_in[0];
    const float* W_ih = (const float*)d_in[1];
    const float* W_hh = (const float*)d_in[2];
    const float* b_ih = (const float*)d_in[3];
    const float* b_hh = (const float*)d_in[4];
    const float* W1   = (const float*)d_in[5];
    const float* b1   = (const float*)d_in[6];
    const float* W2   = (const float*)d_in[7];
    const float* b2   = (const float*)d_in[8];
    float* out = (float*)d_out;

    cudaFuncSetAttribute(xproj_kernel,
                         cudaFuncAttributeMaxDynamicSharedMemorySize, XP_SMEM_BYTES);
    cudaFuncSetAttribute(lstm_loop_kernel,
                         cudaFuncAttributeMaxDynamicSharedMemorySize, SMEM_BYTES);

    xproj_kernel<<<4096, 512, XP_SMEM_BYTES>>>(x, W_ih, b_ih, b_hh);
    lstm_loop_kernel<<<NCTA, 1024, SMEM_BYTES>>>(W_hh, W1, b1, W2, b2, out);
}